// round 6
// baseline (speedup 1.0000x reference)
#include <cuda_runtime.h>
#include <cstdint>

typedef unsigned long long u64;

#define NTHREADS 256
#define F4PT 4                        // float4 per thread per tile
#define EPT (F4PT * 4)                // 16 elems/thread/tile
#define PAIRS (EPT / 2)
#define TILE_ELEMS (NTHREADS * EPT)   // 4096
#define TILE_BYTES (TILE_ELEMS * 4)   // 16384
#define STAGES 2
#define GRID_CTAS (148 * 4)

// ---- constants from the reference (compile-time) ----
#define HCONST { -0.4542235f, 0.7169895f, 0.44056657f, 0.24707365f, \
                 -0.35661384f, 2.5729966f, 4.1841526f, 1.098845f,   \
                 1.553965f, 1.2579314f, 1.1466882f, 1.9164954f,     \
                 2.775174f, 1.2413996f, -3.303845f, 3.1743326f }
#define DCONST { 0.6011055f, 0.32070085f, 0.1728974f, 0.07595864f,  \
                 -0.04305187f, -0.0706069f, -0.02941904f, -0.13304795f, \
                 -0.07925092f, -0.07016345f, 0.39347357f, 0.43960708f,  \
                 -0.01215541f, 0.28329173f, -0.036314f, -0.02618981f }
#define TCONST { 0.7052508f, 0.35964987f, 0.10623224f, -0.04634768f, \
                 0.8112458f, -0.24774243f, -0.44142142f, -1.3476763f, \
                 -0.4575439f, -1.9938357f, 0.99998903f, 0.99853265f,  \
                 0.82849f, 0.57890254f, -2.021475f, -2.7414792f }

// ---- packed f32x2 helpers ----
__device__ __forceinline__ u64 pack2(float lo, float hi) {
    u64 r; asm("mov.b64 %0, {%1, %2};" : "=l"(r) : "f"(lo), "f"(hi)); return r;
}
__device__ __forceinline__ void unpack2(u64 p, float& lo, float& hi) {
    asm("mov.b64 {%0, %1}, %2;" : "=f"(lo), "=f"(hi) : "l"(p));
}
__device__ __forceinline__ u64 ffma2(u64 a, u64 b, u64 c) {
    u64 d; asm("fma.rn.f32x2 %0, %1, %2, %3;" : "=l"(d) : "l"(a), "l"(b), "l"(c)); return d;
}
__device__ __forceinline__ u64 fmul2(u64 a, u64 b) {
    u64 d; asm("mul.rn.f32x2 %0, %1, %2;" : "=l"(d) : "l"(a), "l"(b)); return d;
}
__device__ __forceinline__ float fset_gt(float a, float b) {
    float d; asm("set.gt.f32.f32 %0, %1, %2;" : "=f"(d) : "f"(a), "f"(b)); return d;
}

// ---- mbarrier / bulk-copy helpers ----
__device__ __forceinline__ uint32_t smem_u32(const void* p) {
    uint32_t a;
    asm("{ .reg .u64 t; cvta.to.shared.u64 t, %1; cvt.u32.u64 %0, t; }" : "=r"(a) : "l"(p));
    return a;
}
__device__ __forceinline__ void mbar_init(uint32_t mbar, uint32_t cnt) {
    asm volatile("mbarrier.init.shared.b64 [%0], %1;" :: "r"(mbar), "r"(cnt) : "memory");
}
__device__ __forceinline__ void mbar_expect_tx(uint32_t mbar, uint32_t bytes) {
    asm volatile("mbarrier.arrive.expect_tx.shared.b64 _, [%0], %1;"
                 :: "r"(mbar), "r"(bytes) : "memory");
}
__device__ __forceinline__ void mbar_wait(uint32_t mbar, uint32_t phase) {
    asm volatile(
        "{\n\t.reg .pred P;\n"
        "LW_%=:\n\t"
        "mbarrier.try_wait.parity.acquire.cta.shared::cta.b64 P, [%0], %1, 0x989680;\n\t"
        "@!P bra LW_%=;\n\t}"
        :: "r"(mbar), "r"(phase) : "memory");
}
__device__ __forceinline__ void bulk_g2s(uint32_t dst_smem, const void* src,
                                         uint32_t bytes, uint32_t mbar) {
    asm volatile(
        "cp.async.bulk.shared::cta.global.mbarrier::complete_tx::bytes [%0], [%1], %2, [%3];"
        :: "r"(dst_smem), "l"(src), "r"(bytes), "r"(mbar) : "memory");
}
__device__ __forceinline__ void fence_proxy_async_shared() {
    asm volatile("fence.proxy.async.shared::cta;" ::: "memory");
}

// Core 16-step recurrence on one per-thread tile slice (registers).
__device__ __forceinline__ void spike_tile(const float4 buf[F4PT], float4 res[F4PT]) {
    const float H[16] = HCONST;
    const float D[16] = DCONST;
    const float T[16] = TCONST;

    float vl[PAIRS], vh[PAIRS];
    u64 v2[PAIRS], o2[PAIRS], z2[PAIRS];

#pragma unroll
    for (int j = 0; j < F4PT; j++) {
        vl[2 * j]     = buf[j].x; vh[2 * j]     = buf[j].y;
        vl[2 * j + 1] = buf[j].z; vh[2 * j + 1] = buf[j].w;
        v2[2 * j]     = pack2(buf[j].x, buf[j].y);
        v2[2 * j + 1] = pack2(buf[j].z, buf[j].w);
    }

    {   // step 0: z starts 0 -> o = z*d0, no v update
        const u64 d2 = pack2(D[0], D[0]);
#pragma unroll
        for (int p = 0; p < PAIRS; p++) {
            z2[p] = pack2(fset_gt(vl[p], T[0]), fset_gt(vh[p], T[0]));
            o2[p] = fmul2(z2[p], d2);
        }
    }

#pragma unroll
    for (int k = 1; k < 16; k++) {
        const u64 nh2 = pack2(-H[k], -H[k]);
        const u64 d2  = pack2(D[k], D[k]);
#pragma unroll
        for (int p = 0; p < PAIRS; p++) {
            v2[p] = ffma2(z2[p], nh2, v2[p]);   // v -= z*h (bit-exact)
            unpack2(v2[p], vl[p], vh[p]);
            z2[p] = pack2(fset_gt(vl[p], T[k]), fset_gt(vh[p], T[k]));
            o2[p] = ffma2(z2[p], d2, o2[p]);    // o += z*d
        }
    }

#pragma unroll
    for (int j = 0; j < F4PT; j++) {
        float ox, oy, oz, ow;
        unpack2(o2[2 * j], ox, oy);
        unpack2(o2[2 * j + 1], oz, ow);
        res[j] = make_float4(ox, oy, oz, ow);
    }
}

// Persistent kernel: 2-stage smem ring filled with cp.async.bulk; compute
// reads staged tiles via LDS.128. Prefetch depth lives in smem, not registers.
__global__ void __launch_bounds__(NTHREADS, 4)
spike_pipe_kernel(const float* __restrict__ x, float* __restrict__ out, int ntiles) {
    __shared__ __align__(16) char sbuf[STAGES][TILE_BYTES];
    __shared__ u64 mbar_storage[STAGES];

    const int tid  = threadIdx.x;
    const int grid = gridDim.x;
    const int bid  = blockIdx.x;

    const uint32_t mb0 = smem_u32(&mbar_storage[0]);
    const uint32_t mb1 = smem_u32(&mbar_storage[1]);
    const uint32_t sb0 = smem_u32(&sbuf[0][0]);
    const uint32_t sb1 = smem_u32(&sbuf[1][0]);

    if (tid == 0) {
        mbar_init(mb0, 1);
        mbar_init(mb1, 1);
        fence_proxy_async_shared();
    }
    __syncthreads();

    // number of tiles this CTA handles
    const int count = (bid < ntiles) ? ((ntiles - bid - 1) / grid + 1) : 0;

    // prologue: fill both stages
    if (tid == 0) {
        if (count > 0) {
            mbar_expect_tx(mb0, TILE_BYTES);
            bulk_g2s(sb0, x + (size_t)bid * TILE_ELEMS, TILE_BYTES, mb0);
        }
        if (count > 1) {
            mbar_expect_tx(mb1, TILE_BYTES);
            bulk_g2s(sb1, x + ((size_t)bid + grid) * TILE_ELEMS, TILE_BYTES, mb1);
        }
    }

    for (int i = 0; i < count; i++) {
        const int s = i & 1;
        const uint32_t ph = (uint32_t)((i >> 1) & 1);
        const uint32_t sb = s ? sb1 : sb0;
        const uint32_t mb = s ? mb1 : mb0;

        mbar_wait(mb, ph);

        // read my 16 elems from the staged tile
        float4 buf[F4PT];
        const char* base = (const char*)&sbuf[s][0];
#pragma unroll
        for (int j = 0; j < F4PT; j++) {
            buf[j] = *reinterpret_cast<const float4*>(base + (size_t)tid * 16 + (size_t)j * (NTHREADS * 16));
        }

        float4 res[F4PT];
        spike_tile(buf, res);

        const size_t gtile = (size_t)bid + (size_t)i * grid;
        float4* ob = (float4*)(out + gtile * TILE_ELEMS) + tid;
#pragma unroll
        for (int j = 0; j < F4PT; j++) __stcs(ob + j * NTHREADS, res[j]);

        __syncthreads();  // all lanes done reading stage s

        if (tid == 0 && (i + 2) < count) {
            const size_t ntile = (size_t)bid + (size_t)(i + 2) * grid;
            mbar_expect_tx(mb, TILE_BYTES);
            bulk_g2s(sb, x + ntile * TILE_ELEMS, TILE_BYTES, mb);
        }
        (void)sb;
    }
}

// Generic scalar fallback (any n); never launched for the bench shape.
__global__ void __launch_bounds__(NTHREADS)
spike_generic_kernel(const float* __restrict__ x, float* __restrict__ out, int n) {
    const float H[16] = HCONST;
    const float D[16] = DCONST;
    const float T[16] = TCONST;
    int idx = blockIdx.x * NTHREADS + threadIdx.x;
    if (idx >= n) return;
    float v = x[idx], o = 0.0f;
    bool z = false;
#pragma unroll
    for (int k = 0; k < 16; k++) {
        if (z) v -= H[k];
        z = v > T[k];
        if (z) o += D[k];
    }
    out[idx] = o;
}

extern "C" void kernel_launch(void* const* d_in, const int* in_sizes, int n_in,
                              void* d_out, int out_size) {
    const float* x = (const float*)d_in[0];
    float* out = (float*)d_out;
    int n = in_sizes[0];

    if (n % TILE_ELEMS == 0) {
        int ntiles = n / TILE_ELEMS;
        int grid = GRID_CTAS;
        if (grid > ntiles) grid = ntiles;
        spike_pipe_kernel<<<grid, NTHREADS>>>(x, out, ntiles);
    } else {
        int blocks = (n + NTHREADS - 1) / NTHREADS;
        spike_generic_kernel<<<blocks, NTHREADS>>>(x, out, n);
    }
}